// round 13
// baseline (speedup 1.0000x reference)
#include <cuda_runtime.h>
#include <cuda_fp16.h>
#include <cstdint>
#include <math.h>

#define MAXE 500000
#define CC 128
#define HH 256
#define ED 72
#define CUTOFF_F 6.0f
#define EPS_F 1e-9f

// 30 weight stages of 8KB (4096 halfs) each: k32 x n128 fp16, fragment-packed (R7 layout)
// s 0-5:  W1  np=s/3, kp=s%3   (K padded 72->96)
// s 6-21: W2  t=s-6: np=t>>3, kp=t&7
// s 22-29:W3  kp=s-22, np=0
#define NSTAGES 30

__device__ int g_nact;
__device__ int g_ninact;
__device__ int g_active[MAXE];
__device__ int g_inactive[MAXE];
__device__ float g_const_row[CC];
__device__ __align__(16) __half g_Wph[NSTAGES * 4096];

// ---------------- helpers ----------------
__device__ __forceinline__ uint32_t smem_u32(const void* p) {
    uint32_t a;
    asm("{ .reg .u64 t; cvta.to.shared.u64 t, %1; cvt.u32.u64 %0, t; }" : "=r"(a) : "l"(p));
    return a;
}
__device__ __forceinline__ uint32_t pack_h2(float lo, float hi) {
    uint32_t h;
    asm("cvt.rn.f16x2.f32 %0, %1, %2;" : "=r"(h) : "f"(hi), "f"(lo));
    return h;
}
__device__ __forceinline__ void mma16(float c[4], uint4 a, uint32_t b0, uint32_t b1) {
    asm volatile(
        "mma.sync.aligned.m16n8k16.row.col.f32.f16.f16.f32 "
        "{%0,%1,%2,%3},{%4,%5,%6,%7},{%8,%9},{%0,%1,%2,%3};"
        : "+f"(c[0]), "+f"(c[1]), "+f"(c[2]), "+f"(c[3])
        : "r"(a.x), "r"(a.y), "r"(a.z), "r"(a.w), "r"(b0), "r"(b1));
}
// Newton-on-FMA silu (R7-validated). Keeps the reciprocal OFF the MUFU pipe.
__device__ __forceinline__ float silu_fast(float x) {
    float xc = fminf(fmaxf(x, -30.0f), 30.0f);
    float t = __expf(-xc);
    float z = 1.0f + t;
    float r = __uint_as_float(0x7EF127EAu - __float_as_uint(z));
    r = r * (2.0f - z * r);
    r = r * (2.0f - z * r);
    return x * r;
}
__device__ __forceinline__ float silu_exact(float x) { return x / (1.0f + expf(-x)); }
__device__ __forceinline__ void warp_red2(float &s, float &q) {
#pragma unroll
    for (int o = 16; o > 0; o >>= 1) {
        s += __shfl_xor_sync(0xffffffffu, s, o);
        q += __shfl_xor_sync(0xffffffffu, q, o);
    }
}

// ---------------- small kernels ----------------
__global__ void reset_kernel() { g_nact = 0; g_ninact = 0; }

// pack weights into fp16 fragment layout (R7 LDS.64 layout)
__global__ __launch_bounds__(256) void prepw_kernel(
    const float* __restrict__ W1, const float* __restrict__ W2, const float* __restrict__ W3)
{
    int i = blockIdx.x * 256 + threadIdx.x;   // 30*4096 = 122880
    if (i >= NSTAGES * 4096) return;
    int s = i >> 12, e = i & 4095;
    int h = e & 3;
    int lane = (e >> 2) & 31;
    int nt = (e >> 7) & 3;
    int kk = (e >> 9) & 1;
    int wcx = (e >> 10) & 3;
    int k_loc = kk * 16 + (h >> 1) * 8 + (lane & 3) * 2 + (h & 1);
    int n_loc = wcx * 32 + nt * 8 + (lane >> 2);
    float v;
    if (s < 6) {
        int np = s / 3, kp = s % 3;
        int k = kp * 32 + k_loc, n = np * 128 + n_loc;
        v = (k < ED) ? W1[k * HH + n] : 0.0f;
    } else if (s < 22) {
        int t = s - 6, np = t >> 3, kp = t & 7;
        int k = kp * 32 + k_loc, n = np * 128 + n_loc;
        v = W2[k * HH + n];
    } else {
        int kp = s - 22;
        int k = kp * 32 + k_loc;
        v = W3[k * CC + n_loc];
    }
    g_Wph[i] = __float2half_rn(v);
}

// parallel const-row: 1024 threads, k split x4, smem reduce (validated R11/R12)
__global__ __launch_bounds__(1024) void const_row_kernel(
    const float* __restrict__ b1, const float* __restrict__ W2, const float* __restrict__ b2,
    const float* __restrict__ W3, const float* __restrict__ b3,
    const float* __restrict__ eln_w, const float* __restrict__ eln_b)
{
    __shared__ float s1[HH], s2[HH], red[4][HH], stats[2];
    int tix = threadIdx.x;
    int t = tix & 255, kg = tix >> 8;
    if (tix < HH) s1[tix] = silu_exact(b1[tix]);
    __syncthreads();
    {
        float p = 0.0f;
        int k0 = kg * 64;
#pragma unroll 8
        for (int k = 0; k < 64; k++) p += s1[k0 + k] * W2[(k0 + k) * HH + t];
        red[kg][t] = p;
    }
    __syncthreads();
    if (tix < HH)
        s2[tix] = silu_exact(b2[tix] + red[0][tix] + red[1][tix] + red[2][tix] + red[3][tix]);
    __syncthreads();
    if (t < CC) {
        float p = 0.0f;
        int k0 = kg * 64;
#pragma unroll 8
        for (int k = 0; k < 64; k++) p += s2[k0 + k] * W3[(k0 + k) * CC + t];
        red[kg][t] = p;
    }
    __syncthreads();
    float val = 0.0f;
    if (tix < CC) {
        val = b3[tix] + red[0][tix] + red[1][tix] + red[2][tix] + red[3][tix];
        s1[tix] = val;
    }
    __syncthreads();
    if (tix == 0) {
        float s = 0.f, sq = 0.f;
        for (int k = 0; k < CC; k++) { s += s1[k]; sq += s1[k] * s1[k]; }
        float mu = s / CC, var = sq / CC - mu * mu;
        stats[0] = mu; stats[1] = rsqrtf(var + 1e-5f);
    }
    __syncthreads();
    if (tix < CC) g_const_row[tix] = (val - stats[0]) * stats[1] * eln_w[tix] + eln_b[tix];
}

__global__ __launch_bounds__(256) void node_kernel(
    const int* __restrict__ Z, const float* __restrict__ zt,
    const float* __restrict__ w, const float* __restrict__ b,
    float* __restrict__ out, int N)
{
    int row = blockIdx.x * 8 + (threadIdx.x >> 5);
    int lane = threadIdx.x & 31;
    if (row >= N) return;
    float4 v = *(const float4*)(zt + (size_t)Z[row] * CC + lane * 4);
    float s = v.x + v.y + v.z + v.w;
    float q = v.x * v.x + v.y * v.y + v.z * v.z + v.w * v.w;
    warp_red2(s, q);
    float mu = s / CC, var = q / CC - mu * mu, rs = rsqrtf(var + 1e-5f);
    float4 wv = *(const float4*)(w + lane * 4);
    float4 bv = *(const float4*)(b + lane * 4);
    float4 o;
    o.x = (v.x - mu) * rs * wv.x + bv.x; o.y = (v.y - mu) * rs * wv.y + bv.y;
    o.z = (v.z - mu) * rs * wv.z + bv.z; o.w = (v.w - mu) * rs * wv.w + bv.w;
    *(float4*)(out + (size_t)row * CC + lane * 4) = o;
}

__global__ __launch_bounds__(256) void prep_kernel(
    const float* __restrict__ pos, const int* __restrict__ snd,
    const int* __restrict__ rcv, int E)
{
    int i = blockIdx.x * blockDim.x + threadIdx.x;
    if (i >= E) return;
    int s = snd[i], r = rcv[i];
    float dx = pos[3 * r] - pos[3 * s], dy = pos[3 * r + 1] - pos[3 * s + 1], dz = pos[3 * r + 2] - pos[3 * s + 2];
    float d = sqrtf(dx * dx + dy * dy + dz * dz);
    if (d < CUTOFF_F) { g_active[atomicAdd(&g_nact, 1)] = i; }
    else              { g_inactive[atomicAdd(&g_ninact, 1)] = i; }
}

__global__ __launch_bounds__(256) void fill_kernel(float* __restrict__ out_edge)
{
    int gw = (blockIdx.x * blockDim.x + threadIdx.x) >> 5;
    int lane = threadIdx.x & 31;
    if (gw >= g_ninact) return;
    int e = g_inactive[gw];
    float4 v = *(const float4*)(g_const_row + lane * 4);
    *(float4*)(out_edge + (size_t)e * CC + lane * 4) = v;
}

// ---------------- fused MLP kernel (fp16 mma, 64 edges/CTA, 2 CTAs/SM) — R7 pipeline verbatim ----------------
// SMEM byte offsets
#define RING_B   0        // 3 x 8192 = 24576
#define A2_B     24576    // 32768 (SOUT aliases here: 64*132*4 = 33792, spills 1KB into A1)
#define A1_B     57344    // 12288
#define A3_B     69632    // 32768
#define B1_B     102400   // 1024
#define B2_B     103424   // 1024
#define B3_B     104448   // 512
#define ELNW_B   104960   // 512
#define ELNB_B   105472   // 512
#define EIDX_B   105984   // 256
#define SMEM_BYTES 106496
#define SOUT_B   A2_B

__device__ __forceinline__ void issue_stage(uint32_t ring_u32, int s, int tid) {
    if (s < NSTAGES) {
        int slot = s % 3;
        uint32_t dst = ring_u32 + (uint32_t)slot * 8192u + (uint32_t)tid * 32u;
        const char* src = (const char*)g_Wph + (size_t)s * 8192 + tid * 32;
        asm volatile("cp.async.cg.shared.global [%0], [%1], 16;" :: "r"(dst), "l"(src) : "memory");
        asm volatile("cp.async.cg.shared.global [%0], [%1], 16;" :: "r"(dst + 16u), "l"(src + 16) : "memory");
    }
    asm volatile("cp.async.commit_group;" ::: "memory");
}

__device__ __forceinline__ void gemm_run(
    const char* __restrict__ Abuf, int KS, int nkp,
    char* __restrict__ smc, uint32_t ring_u32, int &st,
    int tid, int mg, int wc, int lane, float acc[2][4][4])
{
    for (int kp = 0; kp < nkp; kp++) {
        asm volatile("cp.async.wait_group 1;" ::: "memory");
        __syncthreads();
        issue_stage(ring_u32, st + 2, tid);
        const char* bs = smc + RING_B + (st % 3) * 8192;
#pragma unroll
        for (int kk = 0; kk < 2; kk++) {
            int ksA = kp * 2 + kk;
            uint4 a[2];
#pragma unroll
            for (int mi = 0; mi < 2; mi++)
                a[mi] = *(const uint4*)(Abuf + (((2 * mg + mi) * KS + ksA) * 32 + lane) * 16);
#pragma unroll
            for (int nt = 0; nt < 4; nt++) {
                uint2 b = *(const uint2*)(bs + (((wc * 2 + kk) * 4 + nt) * 32 + lane) * 8);
#pragma unroll
                for (int mi = 0; mi < 2; mi++)
                    mma16(acc[mi][nt], a[mi], b.x, b.y);
            }
        }
        st++;
    }
}

// epilogue: acc + bias -> silu -> fp16 -> A-fragment layout (KS=16)
__device__ __forceinline__ void epi_silu(
    float acc[2][4][4], int np, const float* __restrict__ bs,
    char* __restrict__ Adst, int mg, int wc, int lane)
{
#pragma unroll
    for (int mi = 0; mi < 2; mi++) {
        int mt = 2 * mg + mi;
#pragma unroll
        for (int nt = 0; nt < 4; nt++) {
            int cb = np * 128 + wc * 32 + nt * 8 + 2 * (lane & 3);
            float v0 = silu_fast(acc[mi][nt][0] + bs[cb]);
            float v1 = silu_fast(acc[mi][nt][1] + bs[cb + 1]);
            float v2 = silu_fast(acc[mi][nt][2] + bs[cb]);
            float v3 = silu_fast(acc[mi][nt][3] + bs[cb + 1]);
            uint32_t h01 = pack_h2(v0, v1);
            uint32_t h23 = pack_h2(v2, v3);
            int ks = np * 8 + wc * 2 + (nt >> 1);
            uint32_t off = ((((mt * 16 + ks) * 32 + lane) * 4 + (nt & 1) * 2)) * 4u;
            *(uint2*)(Adst + off) = make_uint2(h01, h23);
        }
    }
}

__global__ __launch_bounds__(256, 2) void mlp_kernel(
    const float* __restrict__ pos, const int* __restrict__ snd, const int* __restrict__ rcv,
    const float* __restrict__ b1, const float* __restrict__ b2, const float* __restrict__ b3,
    const float* __restrict__ eln_w, const float* __restrict__ eln_b,
    float* __restrict__ out_edge)
{
    extern __shared__ char smc[];
    int tid = threadIdx.x;
    int wid = tid >> 5, lane = tid & 31;
    int base = blockIdx.x * 64;
    int nact = g_nact;
    if (base >= nact) return;
    int count = min(64, nact - base);

    uint32_t ring_u32 = smem_u32(smc);
    int* eidx = (int*)(smc + EIDX_B);
    float* B1s = (float*)(smc + B1_B);
    float* B2s = (float*)(smc + B2_B);
    float* B3s = (float*)(smc + B3_B);

    B1s[tid] = b1[tid];
    B2s[tid] = b2[tid];
    if (tid < 128) {
        B3s[tid] = b3[tid];
        ((float*)(smc + ELNW_B))[tid] = eln_w[tid];
        ((float*)(smc + ELNB_B))[tid] = eln_b[tid];
    }
    if (tid < 64) eidx[tid] = (tid < count) ? g_active[base + tid] : 0;
    __syncthreads();

    issue_stage(ring_u32, 0, tid);
    issue_stage(ring_u32, 1, tid);

    // ---- features -> A1 fragment layout (4 threads per edge; part3 covers k-pad zeros) ----
    {
        int e = tid >> 2, part = tid & 3;
        if (e < count) {
            float rbfe[8], sh[9];
            {
                int ei = eidx[e];
                int ss = snd[ei], rr = rcv[ei];
                float vx = pos[3 * rr] - pos[3 * ss];
                float vy = pos[3 * rr + 1] - pos[3 * ss + 1];
                float vz = pos[3 * rr + 2] - pos[3 * ss + 2];
                float d = sqrtf(vx * vx + vy * vy + vz * vz);
                float inv = 1.0f / (d + EPS_F);
                float x = vx * inv, y = vy * inv, z = vz * inv;
                const float s3 = 1.7320508075688772f, s5 = 2.2360679774997896f, s15 = 3.8729833462074170f;
                sh[0] = 1.0f; sh[1] = s3 * x; sh[2] = s3 * y; sh[3] = s3 * z;
                sh[4] = s15 * x * y; sh[5] = s15 * y * z;
                sh[6] = 0.5f * s5 * (3.0f * z * z - 1.0f);
                sh[7] = s15 * x * z; sh[8] = 0.5f * s15 * (x * x - y * y);
                float xd = d * (1.0f / CUTOFF_F);
                float xp = xd * xd; xp = xp * xp;
                float env = 1.0f - 15.0f * xp + 24.0f * xp * xd - 10.0f * xp * xd * xd;
                const float pref = 0.5773502691896258f;
                const float PI_F = 3.14159265358979323846f;
#pragma unroll
                for (int n = 0; n < 8; n++)
                    rbfe[n] = pref * __sinf((float)(n + 1) * PI_F * xd) * inv * env;
            }
            uint32_t* A1u = (uint32_t*)(smc + A1_B);
            int mt = e >> 4;
            int lnb = (e & 7) * 4;
            int ahi = (e & 15) >> 3;
#pragma unroll
            for (int kq = 0; kq < 12; kq++) {
                int k = part * 24 + kq * 2;
                float v0 = (k < ED) ? rbfe[k / 9] * sh[k % 9] : 0.0f;
                float v1 = ((k + 1) < ED) ? rbfe[(k + 1) / 9] * sh[(k + 1) % 9] : 0.0f;
                uint32_t h = pack_h2(v0, v1);
                int ks = k >> 4;
                int ln = lnb + ((k & 7) >> 1);
                int reg = ((k & 15) >> 3) * 2 + ahi;
                A1u[((mt * 6 + ks) * 32 + ln) * 4 + reg] = h;
            }
        }
    }
    __syncthreads();

    int mg = wid & 1;        // rows 32*mg .. 32*mg+31
    int wc = wid >> 1;       // cols 32*wc .. 32*wc+31
    float acc[2][4][4];
    int st = 0;

#define ZACC() do { \
    _Pragma("unroll") for (int a = 0; a < 2; a++) \
    _Pragma("unroll") for (int b = 0; b < 4; b++) \
    _Pragma("unroll") for (int c = 0; c < 4; c++) acc[a][b][c] = 0.0f; } while (0)

    // ---- GEMM1: A1[64x96] x W1 -> silu -> A2 ----
    ZACC();
    gemm_run(smc + A1_B, 6, 3, smc, ring_u32, st, tid, mg, wc, lane, acc);
    epi_silu(acc, 0, B1s, smc + A2_B, mg, wc, lane);
    ZACC();
    gemm_run(smc + A1_B, 6, 3, smc, ring_u32, st, tid, mg, wc, lane, acc);
    epi_silu(acc, 1, B1s, smc + A2_B, mg, wc, lane);
    __syncthreads();

    // ---- GEMM2: A2[64x256] x W2 -> silu -> A3 ----
    ZACC();
    gemm_run(smc + A2_B, 16, 8, smc, ring_u32, st, tid, mg, wc, lane, acc);
    epi_silu(acc, 0, B2s, smc + A3_B, mg, wc, lane);
    ZACC();
    gemm_run(smc + A2_B, 16, 8, smc, ring_u32, st, tid, mg, wc, lane, acc);
    epi_silu(acc, 1, B2s, smc + A3_B, mg, wc, lane);
    __syncthreads();

    // ---- GEMM3: A3[64x256] x W3 -> +b3 -> SOUT ----
    ZACC();
    gemm_run(smc + A3_B, 16, 8, smc, ring_u32, st, tid, mg, wc, lane, acc);

    {
        float* SOUT = (float*)(smc + SOUT_B);   // [64][132]
#pragma unroll
        for (int mi = 0; mi < 2; mi++) {
            int r0 = (2 * mg + mi) * 16 + (lane >> 2);
#pragma unroll
            for (int nt = 0; nt < 4; nt++) {
                int cb = wc * 32 + nt * 8 + 2 * (lane & 3);
                SOUT[r0 * 132 + cb]           = acc[mi][nt][0] + B3s[cb];
                SOUT[r0 * 132 + cb + 1]       = acc[mi][nt][1] + B3s[cb + 1];
                SOUT[(r0 + 8) * 132 + cb]     = acc[mi][nt][2] + B3s[cb];
                SOUT[(r0 + 8) * 132 + cb + 1] = acc[mi][nt][3] + B3s[cb + 1];
            }
        }
    }
    __syncthreads();

    // ---- layernorm + scatter: warp w handles rows 8w..8w+7 ----
    {
        const float* SOUT = (const float*)(smc + SOUT_B);
        float4 wv = *(const float4*)((const float*)(smc + ELNW_B) + lane * 4);
        float4 bv = *(const float4*)((const float*)(smc + ELNB_B) + lane * 4);
#pragma unroll
        for (int rr = 0; rr < 8; rr++) {
            int row = wid * 8 + rr;
            if (row >= count) continue;
            float4 v = *(const float4*)(SOUT + row * 132 + lane * 4);
            float s = v.x + v.y + v.z + v.w;
            float q = v.x * v.x + v.y * v.y + v.z * v.z + v.w * v.w;
            warp_red2(s, q);
            float mu = s * (1.0f / CC);
            float var = q * (1.0f / CC) - mu * mu;
            float rs = rsqrtf(var + 1e-5f);
            float4 o;
            o.x = (v.x - mu) * rs * wv.x + bv.x;
            o.y = (v.y - mu) * rs * wv.y + bv.y;
            o.z = (v.z - mu) * rs * wv.z + bv.z;
            o.w = (v.w - mu) * rs * wv.w + bv.w;
            *(float4*)(out_edge + (size_t)eidx[row] * CC + lane * 4) = o;
        }
    }
}

// ---------------- launch ----------------
extern "C" void kernel_launch(void* const* d_in, const int* in_sizes, int n_in,
                              void* d_out, int out_size)
{
    const int*   Z     = (const int*)  d_in[0];
    const float* pos   = (const float*)d_in[1];
    const int*   snd   = (const int*)  d_in[2];
    const int*   rcv   = (const int*)  d_in[3];
    const float* zt    = (const float*)d_in[4];
    const float* zln_w = (const float*)d_in[5];
    const float* zln_b = (const float*)d_in[6];
    const float* W1    = (const float*)d_in[7];
    const float* b1    = (const float*)d_in[8];
    const float* W2    = (const float*)d_in[9];
    const float* b2    = (const float*)d_in[10];
    const float* W3    = (const float*)d_in[11];
    const float* b3    = (const float*)d_in[12];
    const float* eln_w = (const float*)d_in[13];
    const float* eln_b = (const float*)d_in[14];

    int N = in_sizes[0];
    int E = in_sizes[2];

    float* out_node = (float*)d_out;
    float* out_edge = out_node + (size_t)N * CC;

    cudaFuncSetAttribute(mlp_kernel, cudaFuncAttributeMaxDynamicSharedMemorySize, SMEM_BYTES);

    // NOTE: launch order keeps mlp_kernel 4th so ncu's capture slot lands on it.
    reset_kernel<<<1, 1>>>();
    prepw_kernel<<<480, 256>>>(W1, W2, W3);
    prep_kernel<<<(E + 255) / 256, 256>>>(pos, snd, rcv, E);
    mlp_kernel<<<(E + 63) / 64, 256, SMEM_BYTES>>>(pos, snd, rcv,
                                                   b1, b2, b3, eln_w, eln_b, out_edge);
    const_row_kernel<<<1, 1024>>>(b1, W2, b2, W3, b3, eln_w, eln_b);
    node_kernel<<<(N + 7) / 8, 256>>>(Z, zt, zln_w, zln_b, out_node, N);
    fill_kernel<<<(E + 7) / 8, 256>>>(out_edge);
}

// round 14
// speedup vs baseline: 1.0383x; 1.0383x over previous
#include <cuda_runtime.h>
#include <cuda_fp16.h>
#include <cstdint>
#include <math.h>

#define MAXE 500000
#define CC 128
#define HH 256
#define ED 72
#define CUTOFF_F 6.0f
#define EPS_F 1e-9f

// 30 weight stages of 8KB (4096 halfs) each: k32 x n128 fp16, fragment-packed (R7 layout)
// s 0-5:  W1  np=s/3, kp=s%3   (K padded 72->96)
// s 6-21: W2  t=s-6: np=t>>3, kp=t&7
// s 22-29:W3  kp=s-22, np=0
#define NSTAGES 30

__device__ int g_nact;
__device__ int g_ninact;
__device__ int g_active[MAXE];
__device__ int g_inactive[MAXE];
__device__ float g_const_row[CC];
__device__ __align__(16) __half g_Wph[NSTAGES * 4096];

// ---------------- helpers ----------------
__device__ __forceinline__ uint32_t smem_u32(const void* p) {
    uint32_t a;
    asm("{ .reg .u64 t; cvta.to.shared.u64 t, %1; cvt.u32.u64 %0, t; }" : "=r"(a) : "l"(p));
    return a;
}
__device__ __forceinline__ uint32_t pack_h2(float lo, float hi) {
    uint32_t h;
    asm("cvt.rn.f16x2.f32 %0, %1, %2;" : "=r"(h) : "f"(hi), "f"(lo));
    return h;
}
__device__ __forceinline__ void mma16(float c[4], uint4 a, uint32_t b0, uint32_t b1) {
    asm volatile(
        "mma.sync.aligned.m16n8k16.row.col.f32.f16.f16.f32 "
        "{%0,%1,%2,%3},{%4,%5,%6,%7},{%8,%9},{%0,%1,%2,%3};"
        : "+f"(c[0]), "+f"(c[1]), "+f"(c[2]), "+f"(c[3])
        : "r"(a.x), "r"(a.y), "r"(a.z), "r"(a.w), "r"(b0), "r"(b1));
}
// Newton-on-FMA silu (R7-validated). Keeps the reciprocal OFF the MUFU pipe.
__device__ __forceinline__ float silu_fast(float x) {
    float xc = fminf(fmaxf(x, -30.0f), 30.0f);
    float t = __expf(-xc);
    float z = 1.0f + t;
    float r = __uint_as_float(0x7EF127EAu - __float_as_uint(z));
    r = r * (2.0f - z * r);
    r = r * (2.0f - z * r);
    return x * r;
}
__device__ __forceinline__ float silu_exact(float x) { return x / (1.0f + expf(-x)); }
__device__ __forceinline__ void warp_red2(float &s, float &q) {
#pragma unroll
    for (int o = 16; o > 0; o >>= 1) {
        s += __shfl_xor_sync(0xffffffffu, s, o);
        q += __shfl_xor_sync(0xffffffffu, q, o);
    }
}

// ---------------- small kernels ----------------
__global__ void reset_kernel() { g_nact = 0; g_ninact = 0; }

// pack weights into fp16 fragment layout (R7 LDS.64 layout)
__global__ __launch_bounds__(256) void prepw_kernel(
    const float* __restrict__ W1, const float* __restrict__ W2, const float* __restrict__ W3)
{
    int i = blockIdx.x * 256 + threadIdx.x;   // 30*4096 = 122880
    if (i >= NSTAGES * 4096) return;
    int s = i >> 12, e = i & 4095;
    int h = e & 3;
    int lane = (e >> 2) & 31;
    int nt = (e >> 7) & 3;
    int kk = (e >> 9) & 1;
    int wcx = (e >> 10) & 3;
    int k_loc = kk * 16 + (h >> 1) * 8 + (lane & 3) * 2 + (h & 1);
    int n_loc = wcx * 32 + nt * 8 + (lane >> 2);
    float v;
    if (s < 6) {
        int np = s / 3, kp = s % 3;
        int k = kp * 32 + k_loc, n = np * 128 + n_loc;
        v = (k < ED) ? W1[k * HH + n] : 0.0f;
    } else if (s < 22) {
        int t = s - 6, np = t >> 3, kp = t & 7;
        int k = kp * 32 + k_loc, n = np * 128 + n_loc;
        v = W2[k * HH + n];
    } else {
        int kp = s - 22;
        int k = kp * 32 + k_loc;
        v = W3[k * CC + n_loc];
    }
    g_Wph[i] = __float2half_rn(v);
}

// parallel const-row: 1024 threads, k split x4, smem reduce (validated R11/R12/R13)
__global__ __launch_bounds__(1024) void const_row_kernel(
    const float* __restrict__ b1, const float* __restrict__ W2, const float* __restrict__ b2,
    const float* __restrict__ W3, const float* __restrict__ b3,
    const float* __restrict__ eln_w, const float* __restrict__ eln_b)
{
    __shared__ float s1[HH], s2[HH], red[4][HH], stats[2];
    int tix = threadIdx.x;
    int t = tix & 255, kg = tix >> 8;
    if (tix < HH) s1[tix] = silu_exact(b1[tix]);
    __syncthreads();
    {
        float p = 0.0f;
        int k0 = kg * 64;
#pragma unroll 8
        for (int k = 0; k < 64; k++) p += s1[k0 + k] * W2[(k0 + k) * HH + t];
        red[kg][t] = p;
    }
    __syncthreads();
    if (tix < HH)
        s2[tix] = silu_exact(b2[tix] + red[0][tix] + red[1][tix] + red[2][tix] + red[3][tix]);
    __syncthreads();
    if (t < CC) {
        float p = 0.0f;
        int k0 = kg * 64;
#pragma unroll 8
        for (int k = 0; k < 64; k++) p += s2[k0 + k] * W3[(k0 + k) * CC + t];
        red[kg][t] = p;
    }
    __syncthreads();
    float val = 0.0f;
    if (tix < CC) {
        val = b3[tix] + red[0][tix] + red[1][tix] + red[2][tix] + red[3][tix];
        s1[tix] = val;
    }
    __syncthreads();
    if (tix == 0) {
        float s = 0.f, sq = 0.f;
        for (int k = 0; k < CC; k++) { s += s1[k]; sq += s1[k] * s1[k]; }
        float mu = s / CC, var = sq / CC - mu * mu;
        stats[0] = mu; stats[1] = rsqrtf(var + 1e-5f);
    }
    __syncthreads();
    if (tix < CC) g_const_row[tix] = (val - stats[0]) * stats[1] * eln_w[tix] + eln_b[tix];
}

__global__ __launch_bounds__(256) void node_kernel(
    const int* __restrict__ Z, const float* __restrict__ zt,
    const float* __restrict__ w, const float* __restrict__ b,
    float* __restrict__ out, int N)
{
    int row = blockIdx.x * 8 + (threadIdx.x >> 5);
    int lane = threadIdx.x & 31;
    if (row >= N) return;
    float4 v = *(const float4*)(zt + (size_t)Z[row] * CC + lane * 4);
    float s = v.x + v.y + v.z + v.w;
    float q = v.x * v.x + v.y * v.y + v.z * v.z + v.w * v.w;
    warp_red2(s, q);
    float mu = s / CC, var = q / CC - mu * mu, rs = rsqrtf(var + 1e-5f);
    float4 wv = *(const float4*)(w + lane * 4);
    float4 bv = *(const float4*)(b + lane * 4);
    float4 o;
    o.x = (v.x - mu) * rs * wv.x + bv.x; o.y = (v.y - mu) * rs * wv.y + bv.y;
    o.z = (v.z - mu) * rs * wv.z + bv.z; o.w = (v.w - mu) * rs * wv.w + bv.w;
    *(float4*)(out + (size_t)row * CC + lane * 4) = o;
}

__global__ __launch_bounds__(256) void prep_kernel(
    const float* __restrict__ pos, const int* __restrict__ snd,
    const int* __restrict__ rcv, int E)
{
    int i = blockIdx.x * blockDim.x + threadIdx.x;
    if (i >= E) return;
    int s = snd[i], r = rcv[i];
    float dx = pos[3 * r] - pos[3 * s], dy = pos[3 * r + 1] - pos[3 * s + 1], dz = pos[3 * r + 2] - pos[3 * s + 2];
    float d = sqrtf(dx * dx + dy * dy + dz * dz);
    if (d < CUTOFF_F) { g_active[atomicAdd(&g_nact, 1)] = i; }
    else              { g_inactive[atomicAdd(&g_ninact, 1)] = i; }
}

__global__ __launch_bounds__(256) void fill_kernel(float* __restrict__ out_edge)
{
    int gw = (blockIdx.x * blockDim.x + threadIdx.x) >> 5;
    int lane = threadIdx.x & 31;
    if (gw >= g_ninact) return;
    int e = g_inactive[gw];
    float4 v = *(const float4*)(g_const_row + lane * 4);
    *(float4*)(out_edge + (size_t)e * CC + lane * 4) = v;
}

// ---------------- fused MLP kernel (fp16 mma, 64 edges/CTA, 2 CTAs/SM) — R7 byte-exact ----------------
// SMEM byte offsets
#define RING_B   0        // 3 x 8192 = 24576
#define A2_B     24576    // 32768 (SOUT aliases here: 64*132*4 = 33792, spills 1KB into A1)
#define A1_B     57344    // 12288
#define A3_B     69632    // 32768
#define B1_B     102400   // 1024
#define B2_B     103424   // 1024
#define B3_B     104448   // 512
#define ELNW_B   104960   // 512
#define ELNB_B   105472   // 512
#define EIDX_B   105984   // 256
#define SMEM_BYTES 106496
#define SOUT_B   A2_B

__device__ __forceinline__ void issue_stage(uint32_t ring_u32, int s, int tid) {
    if (s < NSTAGES) {
        int slot = s % 3;
        uint32_t dst = ring_u32 + (uint32_t)slot * 8192u + (uint32_t)tid * 32u;
        const char* src = (const char*)g_Wph + (size_t)s * 8192 + tid * 32;
        asm volatile("cp.async.cg.shared.global [%0], [%1], 16;" :: "r"(dst), "l"(src) : "memory");
        asm volatile("cp.async.cg.shared.global [%0], [%1], 16;" :: "r"(dst + 16u), "l"(src + 16) : "memory");
    }
    asm volatile("cp.async.commit_group;" ::: "memory");
}

__device__ __forceinline__ void gemm_run(
    const char* __restrict__ Abuf, int KS, int nkp,
    char* __restrict__ smc, uint32_t ring_u32, int &st,
    int tid, int mg, int wc, int lane, float acc[2][4][4])
{
    for (int kp = 0; kp < nkp; kp++) {
        asm volatile("cp.async.wait_group 1;" ::: "memory");
        __syncthreads();
        issue_stage(ring_u32, st + 2, tid);
        const char* bs = smc + RING_B + (st % 3) * 8192;
#pragma unroll
        for (int kk = 0; kk < 2; kk++) {
            int ksA = kp * 2 + kk;
            uint4 a[2];
#pragma unroll
            for (int mi = 0; mi < 2; mi++)
                a[mi] = *(const uint4*)(Abuf + (((2 * mg + mi) * KS + ksA) * 32 + lane) * 16);
#pragma unroll
            for (int nt = 0; nt < 4; nt++) {
                uint2 b = *(const uint2*)(bs + (((wc * 2 + kk) * 4 + nt) * 32 + lane) * 8);
#pragma unroll
                for (int mi = 0; mi < 2; mi++)
                    mma16(acc[mi][nt], a[mi], b.x, b.y);
            }
        }
        st++;
    }
}

// epilogue: acc + bias -> silu -> fp16 -> A-fragment layout (KS=16)
__device__ __forceinline__ void epi_silu(
    float acc[2][4][4], int np, const float* __restrict__ bs,
    char* __restrict__ Adst, int mg, int wc, int lane)
{
#pragma unroll
    for (int mi = 0; mi < 2; mi++) {
        int mt = 2 * mg + mi;
#pragma unroll
        for (int nt = 0; nt < 4; nt++) {
            int cb = np * 128 + wc * 32 + nt * 8 + 2 * (lane & 3);
            float v0 = silu_fast(acc[mi][nt][0] + bs[cb]);
            float v1 = silu_fast(acc[mi][nt][1] + bs[cb + 1]);
            float v2 = silu_fast(acc[mi][nt][2] + bs[cb]);
            float v3 = silu_fast(acc[mi][nt][3] + bs[cb + 1]);
            uint32_t h01 = pack_h2(v0, v1);
            uint32_t h23 = pack_h2(v2, v3);
            int ks = np * 8 + wc * 2 + (nt >> 1);
            uint32_t off = ((((mt * 16 + ks) * 32 + lane) * 4 + (nt & 1) * 2)) * 4u;
            *(uint2*)(Adst + off) = make_uint2(h01, h23);
        }
    }
}

__global__ __launch_bounds__(256, 2) void mlp_kernel(
    const float* __restrict__ pos, const int* __restrict__ snd, const int* __restrict__ rcv,
    const float* __restrict__ b1, const float* __restrict__ b2, const float* __restrict__ b3,
    const float* __restrict__ eln_w, const float* __restrict__ eln_b,
    float* __restrict__ out_edge)
{
    extern __shared__ char smc[];
    int tid = threadIdx.x;
    int wid = tid >> 5, lane = tid & 31;
    int base = blockIdx.x * 64;
    int nact = g_nact;
    if (base >= nact) return;
    int count = min(64, nact - base);

    uint32_t ring_u32 = smem_u32(smc);
    int* eidx = (int*)(smc + EIDX_B);
    float* B1s = (float*)(smc + B1_B);
    float* B2s = (float*)(smc + B2_B);
    float* B3s = (float*)(smc + B3_B);

    B1s[tid] = b1[tid];
    B2s[tid] = b2[tid];
    if (tid < 128) {
        B3s[tid] = b3[tid];
        ((float*)(smc + ELNW_B))[tid] = eln_w[tid];
        ((float*)(smc + ELNB_B))[tid] = eln_b[tid];
    }
    if (tid < 64) eidx[tid] = (tid < count) ? g_active[base + tid] : 0;
    // zero A1 (12288 B = 768 uint4) — R7 exact
    {
        uint4 z = make_uint4(0, 0, 0, 0);
        uint4* a1z = (uint4*)(smc + A1_B);
#pragma unroll
        for (int i = 0; i < 3; i++) a1z[tid + i * 256] = z;
    }
    __syncthreads();

    issue_stage(ring_u32, 0, tid);
    issue_stage(ring_u32, 1, tid);

    // ---- features -> A1 fragment layout (4 threads per edge) — R7 exact ----
    {
        int e = tid >> 2, part = tid & 3;
        if (e < count && part < 3) {
            int ei = eidx[e];
            int ss = snd[ei], rr = rcv[ei];
            float vx = pos[3 * rr] - pos[3 * ss];
            float vy = pos[3 * rr + 1] - pos[3 * ss + 1];
            float vz = pos[3 * rr + 2] - pos[3 * ss + 2];
            float d = sqrtf(vx * vx + vy * vy + vz * vz);
            float inv = 1.0f / (d + EPS_F);
            float x = vx * inv, y = vy * inv, z = vz * inv;
            const float s3 = 1.7320508075688772f, s5 = 2.2360679774997896f, s15 = 3.8729833462074170f;
            float sh[9];
            sh[0] = 1.0f; sh[1] = s3 * x; sh[2] = s3 * y; sh[3] = s3 * z;
            sh[4] = s15 * x * y; sh[5] = s15 * y * z;
            sh[6] = 0.5f * s5 * (3.0f * z * z - 1.0f);
            sh[7] = s15 * x * z; sh[8] = 0.5f * s15 * (x * x - y * y);
            float xd = d * (1.0f / CUTOFF_F);
            float xp = xd * xd; xp = xp * xp;
            float env = 1.0f - 15.0f * xp + 24.0f * xp * xd - 10.0f * xp * xd * xd;
            const float pref = 0.5773502691896258f;
            const float PI_F = 3.14159265358979323846f;
            float rbfe[8];
#pragma unroll
            for (int n = 0; n < 8; n++)
                rbfe[n] = pref * __sinf((float)(n + 1) * PI_F * xd) * inv * env;

            uint32_t* A1u = (uint32_t*)(smc + A1_B);
            int mt = e >> 4;
            int lnb = (e & 7) * 4;
            int ahi = (e & 15) >> 3;
#pragma unroll
            for (int kq = 0; kq < 12; kq++) {
                int k = part * 24 + kq * 2;
                float v0 = rbfe[k / 9] * sh[k % 9];
                float v1 = ((k + 1) < ED) ? rbfe[(k + 1) / 9] * sh[(k + 1) % 9] : 0.0f;
                uint32_t h = pack_h2(v0, v1);
                int ks = k >> 4;
                int ln = lnb + ((k & 7) >> 1);
                int reg = ((k & 15) >> 3) * 2 + ahi;
                A1u[((mt * 6 + ks) * 32 + ln) * 4 + reg] = h;
            }
        }
    }
    __syncthreads();

    int mg = wid & 1;        // rows 32*mg .. 32*mg+31
    int wc = wid >> 1;       // cols 32*wc .. 32*wc+31
    float acc[2][4][4];
    int st = 0;

#define ZACC() do { \
    _Pragma("unroll") for (int a = 0; a < 2; a++) \
    _Pragma("unroll") for (int b = 0; b < 4; b++) \
    _Pragma("unroll") for (int c = 0; c < 4; c++) acc[a][b][c] = 0.0f; } while (0)

    // ---- GEMM1: A1[64x96] x W1 -> silu -> A2 ----
    ZACC();
    gemm_run(smc + A1_B, 6, 3, smc, ring_u32, st, tid, mg, wc, lane, acc);
    epi_silu(acc, 0, B1s, smc + A2_B, mg, wc, lane);
    ZACC();
    gemm_run(smc + A1_B, 6, 3, smc, ring_u32, st, tid, mg, wc, lane, acc);
    epi_silu(acc, 1, B1s, smc + A2_B, mg, wc, lane);
    __syncthreads();

    // ---- GEMM2: A2[64x256] x W2 -> silu -> A3 ----
    ZACC();
    gemm_run(smc + A2_B, 16, 8, smc, ring_u32, st, tid, mg, wc, lane, acc);
    epi_silu(acc, 0, B2s, smc + A3_B, mg, wc, lane);
    ZACC();
    gemm_run(smc + A2_B, 16, 8, smc, ring_u32, st, tid, mg, wc, lane, acc);
    epi_silu(acc, 1, B2s, smc + A3_B, mg, wc, lane);
    __syncthreads();

    // ---- GEMM3: A3[64x256] x W3 -> +b3 -> SOUT ----
    ZACC();
    gemm_run(smc + A3_B, 16, 8, smc, ring_u32, st, tid, mg, wc, lane, acc);

    {
        float* SOUT = (float*)(smc + SOUT_B);   // [64][132]
#pragma unroll
        for (int mi = 0; mi < 2; mi++) {
            int r0 = (2 * mg + mi) * 16 + (lane >> 2);
#pragma unroll
            for (int nt = 0; nt < 4; nt++) {
                int cb = wc * 32 + nt * 8 + 2 * (lane & 3);
                SOUT[r0 * 132 + cb]           = acc[mi][nt][0] + B3s[cb];
                SOUT[r0 * 132 + cb + 1]       = acc[mi][nt][1] + B3s[cb + 1];
                SOUT[(r0 + 8) * 132 + cb]     = acc[mi][nt][2] + B3s[cb];
                SOUT[(r0 + 8) * 132 + cb + 1] = acc[mi][nt][3] + B3s[cb + 1];
            }
        }
    }
    __syncthreads();

    // ---- layernorm + scatter: warp w handles rows 8w..8w+7 ----
    {
        const float* SOUT = (const float*)(smc + SOUT_B);
        float4 wv = *(const float4*)((const float*)(smc + ELNW_B) + lane * 4);
        float4 bv = *(const float4*)((const float*)(smc + ELNB_B) + lane * 4);
#pragma unroll
        for (int rr = 0; rr < 8; rr++) {
            int row = wid * 8 + rr;
            if (row >= count) continue;
            float4 v = *(const float4*)(SOUT + row * 132 + lane * 4);
            float s = v.x + v.y + v.z + v.w;
            float q = v.x * v.x + v.y * v.y + v.z * v.z + v.w * v.w;
            warp_red2(s, q);
            float mu = s * (1.0f / CC);
            float var = q * (1.0f / CC) - mu * mu;
            float rs = rsqrtf(var + 1e-5f);
            float4 o;
            o.x = (v.x - mu) * rs * wv.x + bv.x;
            o.y = (v.y - mu) * rs * wv.y + bv.y;
            o.z = (v.z - mu) * rs * wv.z + bv.z;
            o.w = (v.w - mu) * rs * wv.w + bv.w;
            *(float4*)(out_edge + (size_t)eidx[row] * CC + lane * 4) = o;
        }
    }
}

// ---------------- launch ----------------
extern "C" void kernel_launch(void* const* d_in, const int* in_sizes, int n_in,
                              void* d_out, int out_size)
{
    const int*   Z     = (const int*)  d_in[0];
    const float* pos   = (const float*)d_in[1];
    const int*   snd   = (const int*)  d_in[2];
    const int*   rcv   = (const int*)  d_in[3];
    const float* zt    = (const float*)d_in[4];
    const float* zln_w = (const float*)d_in[5];
    const float* zln_b = (const float*)d_in[6];
    const float* W1    = (const float*)d_in[7];
    const float* b1    = (const float*)d_in[8];
    const float* W2    = (const float*)d_in[9];
    const float* b2    = (const float*)d_in[10];
    const float* W3    = (const float*)d_in[11];
    const float* b3    = (const float*)d_in[12];
    const float* eln_w = (const float*)d_in[13];
    const float* eln_b = (const float*)d_in[14];

    int N = in_sizes[0];
    int E = in_sizes[2];

    float* out_node = (float*)d_out;
    float* out_edge = out_node + (size_t)N * CC;

    cudaFuncSetAttribute(mlp_kernel, cudaFuncAttributeMaxDynamicSharedMemorySize, SMEM_BYTES);

    // NOTE: launch order keeps mlp_kernel 4th so ncu's capture slot lands on it.
    reset_kernel<<<1, 1>>>();
    prepw_kernel<<<480, 256>>>(W1, W2, W3);
    prep_kernel<<<(E + 255) / 256, 256>>>(pos, snd, rcv, E);
    mlp_kernel<<<(E + 63) / 64, 256, SMEM_BYTES>>>(pos, snd, rcv,
                                                   b1, b2, b3, eln_w, eln_b, out_edge);
    const_row_kernel<<<1, 1024>>>(b1, W2, b2, W3, b3, eln_w, eln_b);
    node_kernel<<<(N + 7) / 8, 256>>>(Z, zt, zln_w, zln_b, out_node, N);
    fill_kernel<<<(E + 7) / 8, 256>>>(out_edge);
}

// round 15
// speedup vs baseline: 1.0964x; 1.0560x over previous
#include <cuda_runtime.h>
#include <cuda_fp16.h>
#include <cstdint>
#include <math.h>

#define MAXE 500000
#define CC 128
#define HH 256
#define ED 72
#define CUTOFF_F 6.0f
#define EPS_F 1e-9f

// 30 weight stages of 8KB (4096 halfs) each: k32 x n128 fp16, fragment-packed (R7 layout)
// s 0-5:  W1  np=s/3, kp=s%3   (K padded 72->96)
// s 6-21: W2  t=s-6: np=t>>3, kp=t&7
// s 22-29:W3  kp=s-22, np=0
#define NSTAGES 30

__device__ int g_nact;
__device__ int g_ninact;
__device__ int g_active[MAXE];
__device__ int g_inactive[MAXE];
__device__ float g_const_row[CC];
__device__ __align__(16) __half g_Wph[NSTAGES * 4096];

// ---------------- helpers ----------------
__device__ __forceinline__ uint32_t smem_u32(const void* p) {
    uint32_t a;
    asm("{ .reg .u64 t; cvta.to.shared.u64 t, %1; cvt.u32.u64 %0, t; }" : "=r"(a) : "l"(p));
    return a;
}
__device__ __forceinline__ uint32_t pack_h2(float lo, float hi) {
    uint32_t h;
    asm("cvt.rn.f16x2.f32 %0, %1, %2;" : "=r"(h) : "f"(hi), "f"(lo));
    return h;
}
__device__ __forceinline__ void mma16(float c[4], uint4 a, uint32_t b0, uint32_t b1) {
    asm volatile(
        "mma.sync.aligned.m16n8k16.row.col.f32.f16.f16.f32 "
        "{%0,%1,%2,%3},{%4,%5,%6,%7},{%8,%9},{%0,%1,%2,%3};"
        : "+f"(c[0]), "+f"(c[1]), "+f"(c[2]), "+f"(c[3])
        : "r"(a.x), "r"(a.y), "r"(a.z), "r"(a.w), "r"(b0), "r"(b1));
}
// Newton-on-FMA silu (R7-validated). Keeps the reciprocal OFF the MUFU pipe.
__device__ __forceinline__ float silu_fast(float x) {
    float xc = fminf(fmaxf(x, -30.0f), 30.0f);
    float t = __expf(-xc);
    float z = 1.0f + t;
    float r = __uint_as_float(0x7EF127EAu - __float_as_uint(z));
    r = r * (2.0f - z * r);
    r = r * (2.0f - z * r);
    return x * r;
}
__device__ __forceinline__ float silu_exact(float x) { return x / (1.0f + expf(-x)); }
__device__ __forceinline__ void warp_red2(float &s, float &q) {
#pragma unroll
    for (int o = 16; o > 0; o >>= 1) {
        s += __shfl_xor_sync(0xffffffffu, s, o);
        q += __shfl_xor_sync(0xffffffffu, q, o);
    }
}

// ---------------- small kernels ----------------
__global__ void reset_kernel() { g_nact = 0; g_ninact = 0; }

// pack weights into fp16 fragment layout (R7 LDS.64 layout)
__global__ __launch_bounds__(256) void prepw_kernel(
    const float* __restrict__ W1, const float* __restrict__ W2, const float* __restrict__ W3)
{
    int i = blockIdx.x * 256 + threadIdx.x;   // 30*4096 = 122880
    if (i >= NSTAGES * 4096) return;
    int s = i >> 12, e = i & 4095;
    int h = e & 3;
    int lane = (e >> 2) & 31;
    int nt = (e >> 7) & 3;
    int kk = (e >> 9) & 1;
    int wcx = (e >> 10) & 3;
    int k_loc = kk * 16 + (h >> 1) * 8 + (lane & 3) * 2 + (h & 1);
    int n_loc = wcx * 32 + nt * 8 + (lane >> 2);
    float v;
    if (s < 6) {
        int np = s / 3, kp = s % 3;
        int k = kp * 32 + k_loc, n = np * 128 + n_loc;
        v = (k < ED) ? W1[k * HH + n] : 0.0f;
    } else if (s < 22) {
        int t = s - 6, np = t >> 3, kp = t & 7;
        int k = kp * 32 + k_loc, n = np * 128 + n_loc;
        v = W2[k * HH + n];
    } else {
        int kp = s - 22;
        int k = kp * 32 + k_loc;
        v = W3[k * CC + n_loc];
    }
    g_Wph[i] = __float2half_rn(v);
}

// parallel const-row: 1024 threads, k split x4, smem reduce (validated R11-R14)
__global__ __launch_bounds__(1024) void const_row_kernel(
    const float* __restrict__ b1, const float* __restrict__ W2, const float* __restrict__ b2,
    const float* __restrict__ W3, const float* __restrict__ b3,
    const float* __restrict__ eln_w, const float* __restrict__ eln_b)
{
    __shared__ float s1[HH], s2[HH], red[4][HH], stats[2];
    int tix = threadIdx.x;
    int t = tix & 255, kg = tix >> 8;
    if (tix < HH) s1[tix] = silu_exact(b1[tix]);
    __syncthreads();
    {
        float p = 0.0f;
        int k0 = kg * 64;
#pragma unroll 8
        for (int k = 0; k < 64; k++) p += s1[k0 + k] * W2[(k0 + k) * HH + t];
        red[kg][t] = p;
    }
    __syncthreads();
    if (tix < HH)
        s2[tix] = silu_exact(b2[tix] + red[0][tix] + red[1][tix] + red[2][tix] + red[3][tix]);
    __syncthreads();
    if (t < CC) {
        float p = 0.0f;
        int k0 = kg * 64;
#pragma unroll 8
        for (int k = 0; k < 64; k++) p += s2[k0 + k] * W3[(k0 + k) * CC + t];
        red[kg][t] = p;
    }
    __syncthreads();
    float val = 0.0f;
    if (tix < CC) {
        val = b3[tix] + red[0][tix] + red[1][tix] + red[2][tix] + red[3][tix];
        s1[tix] = val;
    }
    __syncthreads();
    if (tix == 0) {
        float s = 0.f, sq = 0.f;
        for (int k = 0; k < CC; k++) { s += s1[k]; sq += s1[k] * s1[k]; }
        float mu = s / CC, var = sq / CC - mu * mu;
        stats[0] = mu; stats[1] = rsqrtf(var + 1e-5f);
    }
    __syncthreads();
    if (tix < CC) g_const_row[tix] = (val - stats[0]) * stats[1] * eln_w[tix] + eln_b[tix];
}

__global__ __launch_bounds__(256) void node_kernel(
    const int* __restrict__ Z, const float* __restrict__ zt,
    const float* __restrict__ w, const float* __restrict__ b,
    float* __restrict__ out, int N)
{
    int row = blockIdx.x * 8 + (threadIdx.x >> 5);
    int lane = threadIdx.x & 31;
    if (row >= N) return;
    float4 v = *(const float4*)(zt + (size_t)Z[row] * CC + lane * 4);
    float s = v.x + v.y + v.z + v.w;
    float q = v.x * v.x + v.y * v.y + v.z * v.z + v.w * v.w;
    warp_red2(s, q);
    float mu = s / CC, var = q / CC - mu * mu, rs = rsqrtf(var + 1e-5f);
    float4 wv = *(const float4*)(w + lane * 4);
    float4 bv = *(const float4*)(b + lane * 4);
    float4 o;
    o.x = (v.x - mu) * rs * wv.x + bv.x; o.y = (v.y - mu) * rs * wv.y + bv.y;
    o.z = (v.z - mu) * rs * wv.z + bv.z; o.w = (v.w - mu) * rs * wv.w + bv.w;
    *(float4*)(out + (size_t)row * CC + lane * 4) = o;
}

__global__ __launch_bounds__(256) void prep_kernel(
    const float* __restrict__ pos, const int* __restrict__ snd,
    const int* __restrict__ rcv, int E)
{
    int i = blockIdx.x * blockDim.x + threadIdx.x;
    if (i >= E) return;
    int s = snd[i], r = rcv[i];
    float dx = pos[3 * r] - pos[3 * s], dy = pos[3 * r + 1] - pos[3 * s + 1], dz = pos[3 * r + 2] - pos[3 * s + 2];
    float d = sqrtf(dx * dx + dy * dy + dz * dz);
    if (d < CUTOFF_F) { g_active[atomicAdd(&g_nact, 1)] = i; }
    else              { g_inactive[atomicAdd(&g_ninact, 1)] = i; }
}

__global__ __launch_bounds__(256) void fill_kernel(float* __restrict__ out_edge)
{
    int gw = (blockIdx.x * blockDim.x + threadIdx.x) >> 5;
    int lane = threadIdx.x & 31;
    if (gw >= g_ninact) return;
    int e = g_inactive[gw];
    float4 v = *(const float4*)(g_const_row + lane * 4);
    *(float4*)(out_edge + (size_t)e * CC + lane * 4) = v;
}

// ---------------- fused MLP kernel (fp16 mma, 64 edges/CTA, 2 CTAs/SM) — R14/R7 frozen ----------------
// SMEM byte offsets
#define RING_B   0        // 3 x 8192 = 24576
#define A2_B     24576    // 32768 (SOUT aliases here: 64*132*4 = 33792, spills 1KB into A1)
#define A1_B     57344    // 12288
#define A3_B     69632    // 32768
#define B1_B     102400   // 1024
#define B2_B     103424   // 1024
#define B3_B     104448   // 512
#define ELNW_B   104960   // 512
#define ELNB_B   105472   // 512
#define EIDX_B   105984   // 256
#define SMEM_BYTES 106496
#define SOUT_B   A2_B

__device__ __forceinline__ void issue_stage(uint32_t ring_u32, int s, int tid) {
    if (s < NSTAGES) {
        int slot = s % 3;
        uint32_t dst = ring_u32 + (uint32_t)slot * 8192u + (uint32_t)tid * 32u;
        const char* src = (const char*)g_Wph + (size_t)s * 8192 + tid * 32;
        asm volatile("cp.async.cg.shared.global [%0], [%1], 16;" :: "r"(dst), "l"(src) : "memory");
        asm volatile("cp.async.cg.shared.global [%0], [%1], 16;" :: "r"(dst + 16u), "l"(src + 16) : "memory");
    }
    asm volatile("cp.async.commit_group;" ::: "memory");
}

__device__ __forceinline__ void gemm_run(
    const char* __restrict__ Abuf, int KS, int nkp,
    char* __restrict__ smc, uint32_t ring_u32, int &st,
    int tid, int mg, int wc, int lane, float acc[2][4][4])
{
    for (int kp = 0; kp < nkp; kp++) {
        asm volatile("cp.async.wait_group 1;" ::: "memory");
        __syncthreads();
        issue_stage(ring_u32, st + 2, tid);
        const char* bs = smc + RING_B + (st % 3) * 8192;
#pragma unroll
        for (int kk = 0; kk < 2; kk++) {
            int ksA = kp * 2 + kk;
            uint4 a[2];
#pragma unroll
            for (int mi = 0; mi < 2; mi++)
                a[mi] = *(const uint4*)(Abuf + (((2 * mg + mi) * KS + ksA) * 32 + lane) * 16);
#pragma unroll
            for (int nt = 0; nt < 4; nt++) {
                uint2 b = *(const uint2*)(bs + (((wc * 2 + kk) * 4 + nt) * 32 + lane) * 8);
#pragma unroll
                for (int mi = 0; mi < 2; mi++)
                    mma16(acc[mi][nt], a[mi], b.x, b.y);
            }
        }
        st++;
    }
}

// epilogue: acc + bias -> silu -> fp16 -> A-fragment layout (KS=16)
__device__ __forceinline__ void epi_silu(
    float acc[2][4][4], int np, const float* __restrict__ bs,
    char* __restrict__ Adst, int mg, int wc, int lane)
{
#pragma unroll
    for (int mi = 0; mi < 2; mi++) {
        int mt = 2 * mg + mi;
#pragma unroll
        for (int nt = 0; nt < 4; nt++) {
            int cb = np * 128 + wc * 32 + nt * 8 + 2 * (lane & 3);
            float v0 = silu_fast(acc[mi][nt][0] + bs[cb]);
            float v1 = silu_fast(acc[mi][nt][1] + bs[cb + 1]);
            float v2 = silu_fast(acc[mi][nt][2] + bs[cb]);
            float v3 = silu_fast(acc[mi][nt][3] + bs[cb + 1]);
            uint32_t h01 = pack_h2(v0, v1);
            uint32_t h23 = pack_h2(v2, v3);
            int ks = np * 8 + wc * 2 + (nt >> 1);
            uint32_t off = ((((mt * 16 + ks) * 32 + lane) * 4 + (nt & 1) * 2)) * 4u;
            *(uint2*)(Adst + off) = make_uint2(h01, h23);
        }
    }
}

__global__ __launch_bounds__(256, 2) void mlp_kernel(
    const float* __restrict__ pos, const int* __restrict__ snd, const int* __restrict__ rcv,
    const float* __restrict__ b1, const float* __restrict__ b2, const float* __restrict__ b3,
    const float* __restrict__ eln_w, const float* __restrict__ eln_b,
    float* __restrict__ out_edge)
{
    extern __shared__ char smc[];
    int tid = threadIdx.x;
    int wid = tid >> 5, lane = tid & 31;
    int base = blockIdx.x * 64;
    int nact = g_nact;
    if (base >= nact) return;
    int count = min(64, nact - base);

    uint32_t ring_u32 = smem_u32(smc);
    int* eidx = (int*)(smc + EIDX_B);
    float* B1s = (float*)(smc + B1_B);
    float* B2s = (float*)(smc + B2_B);
    float* B3s = (float*)(smc + B3_B);

    B1s[tid] = b1[tid];
    B2s[tid] = b2[tid];
    if (tid < 128) {
        B3s[tid] = b3[tid];
        ((float*)(smc + ELNW_B))[tid] = eln_w[tid];
        ((float*)(smc + ELNB_B))[tid] = eln_b[tid];
    }
    if (tid < 64) eidx[tid] = (tid < count) ? g_active[base + tid] : 0;
    // zero A1 (12288 B = 768 uint4) — R7 exact
    {
        uint4 z = make_uint4(0, 0, 0, 0);
        uint4* a1z = (uint4*)(smc + A1_B);
#pragma unroll
        for (int i = 0; i < 3; i++) a1z[tid + i * 256] = z;
    }
    __syncthreads();

    issue_stage(ring_u32, 0, tid);
    issue_stage(ring_u32, 1, tid);

    // ---- features -> A1 fragment layout (4 threads per edge) — R7 exact ----
    {
        int e = tid >> 2, part = tid & 3;
        if (e < count && part < 3) {
            int ei = eidx[e];
            int ss = snd[ei], rr = rcv[ei];
            float vx = pos[3 * rr] - pos[3 * ss];
            float vy = pos[3 * rr + 1] - pos[3 * ss + 1];
            float vz = pos[3 * rr + 2] - pos[3 * ss + 2];
            float d = sqrtf(vx * vx + vy * vy + vz * vz);
            float inv = 1.0f / (d + EPS_F);
            float x = vx * inv, y = vy * inv, z = vz * inv;
            const float s3 = 1.7320508075688772f, s5 = 2.2360679774997896f, s15 = 3.8729833462074170f;
            float sh[9];
            sh[0] = 1.0f; sh[1] = s3 * x; sh[2] = s3 * y; sh[3] = s3 * z;
            sh[4] = s15 * x * y; sh[5] = s15 * y * z;
            sh[6] = 0.5f * s5 * (3.0f * z * z - 1.0f);
            sh[7] = s15 * x * z; sh[8] = 0.5f * s15 * (x * x - y * y);
            float xd = d * (1.0f / CUTOFF_F);
            float xp = xd * xd; xp = xp * xp;
            float env = 1.0f - 15.0f * xp + 24.0f * xp * xd - 10.0f * xp * xd * xd;
            const float pref = 0.5773502691896258f;
            const float PI_F = 3.14159265358979323846f;
            float rbfe[8];
#pragma unroll
            for (int n = 0; n < 8; n++)
                rbfe[n] = pref * __sinf((float)(n + 1) * PI_F * xd) * inv * env;

            uint32_t* A1u = (uint32_t*)(smc + A1_B);
            int mt = e >> 4;
            int lnb = (e & 7) * 4;
            int ahi = (e & 15) >> 3;
#pragma unroll
            for (int kq = 0; kq < 12; kq++) {
                int k = part * 24 + kq * 2;
                float v0 = rbfe[k / 9] * sh[k % 9];
                float v1 = ((k + 1) < ED) ? rbfe[(k + 1) / 9] * sh[(k + 1) % 9] : 0.0f;
                uint32_t h = pack_h2(v0, v1);
                int ks = k >> 4;
                int ln = lnb + ((k & 7) >> 1);
                int reg = ((k & 15) >> 3) * 2 + ahi;
                A1u[((mt * 6 + ks) * 32 + ln) * 4 + reg] = h;
            }
        }
    }
    __syncthreads();

    int mg = wid & 1;        // rows 32*mg .. 32*mg+31
    int wc = wid >> 1;       // cols 32*wc .. 32*wc+31
    float acc[2][4][4];
    int st = 0;

#define ZACC() do { \
    _Pragma("unroll") for (int a = 0; a < 2; a++) \
    _Pragma("unroll") for (int b = 0; b < 4; b++) \
    _Pragma("unroll") for (int c = 0; c < 4; c++) acc[a][b][c] = 0.0f; } while (0)

    // ---- GEMM1: A1[64x96] x W1 -> silu -> A2 ----
    ZACC();
    gemm_run(smc + A1_B, 6, 3, smc, ring_u32, st, tid, mg, wc, lane, acc);
    epi_silu(acc, 0, B1s, smc + A2_B, mg, wc, lane);
    ZACC();
    gemm_run(smc + A1_B, 6, 3, smc, ring_u32, st, tid, mg, wc, lane, acc);
    epi_silu(acc, 1, B1s, smc + A2_B, mg, wc, lane);
    __syncthreads();

    // ---- GEMM2: A2[64x256] x W2 -> silu -> A3 ----
    ZACC();
    gemm_run(smc + A2_B, 16, 8, smc, ring_u32, st, tid, mg, wc, lane, acc);
    epi_silu(acc, 0, B2s, smc + A3_B, mg, wc, lane);
    ZACC();
    gemm_run(smc + A2_B, 16, 8, smc, ring_u32, st, tid, mg, wc, lane, acc);
    epi_silu(acc, 1, B2s, smc + A3_B, mg, wc, lane);
    __syncthreads();

    // ---- GEMM3: A3[64x256] x W3 -> +b3 -> SOUT ----
    ZACC();
    gemm_run(smc + A3_B, 16, 8, smc, ring_u32, st, tid, mg, wc, lane, acc);

    {
        float* SOUT = (float*)(smc + SOUT_B);   // [64][132]
#pragma unroll
        for (int mi = 0; mi < 2; mi++) {
            int r0 = (2 * mg + mi) * 16 + (lane >> 2);
#pragma unroll
            for (int nt = 0; nt < 4; nt++) {
                int cb = wc * 32 + nt * 8 + 2 * (lane & 3);
                SOUT[r0 * 132 + cb]           = acc[mi][nt][0] + B3s[cb];
                SOUT[r0 * 132 + cb + 1]       = acc[mi][nt][1] + B3s[cb + 1];
                SOUT[(r0 + 8) * 132 + cb]     = acc[mi][nt][2] + B3s[cb];
                SOUT[(r0 + 8) * 132 + cb + 1] = acc[mi][nt][3] + B3s[cb + 1];
            }
        }
    }
    __syncthreads();

    // ---- layernorm + scatter: warp w handles rows 8w..8w+7 ----
    {
        const float* SOUT = (const float*)(smc + SOUT_B);
        float4 wv = *(const float4*)((const float*)(smc + ELNW_B) + lane * 4);
        float4 bv = *(const float4*)((const float*)(smc + ELNB_B) + lane * 4);
#pragma unroll
        for (int rr = 0; rr < 8; rr++) {
            int row = wid * 8 + rr;
            if (row >= count) continue;
            float4 v = *(const float4*)(SOUT + row * 132 + lane * 4);
            float s = v.x + v.y + v.z + v.w;
            float q = v.x * v.x + v.y * v.y + v.z * v.z + v.w * v.w;
            warp_red2(s, q);
            float mu = s * (1.0f / CC);
            float var = q * (1.0f / CC) - mu * mu;
            float rs = rsqrtf(var + 1e-5f);
            float4 o;
            o.x = (v.x - mu) * rs * wv.x + bv.x;
            o.y = (v.y - mu) * rs * wv.y + bv.y;
            o.z = (v.z - mu) * rs * wv.z + bv.z;
            o.w = (v.w - mu) * rs * wv.w + bv.w;
            *(float4*)(out_edge + (size_t)eidx[row] * CC + lane * 4) = o;
        }
    }
}

// ---------------- launch (fork/join captured multi-stream DAG) ----------------
extern "C" void kernel_launch(void* const* d_in, const int* in_sizes, int n_in,
                              void* d_out, int out_size)
{
    const int*   Z     = (const int*)  d_in[0];
    const float* pos   = (const float*)d_in[1];
    const int*   snd   = (const int*)  d_in[2];
    const int*   rcv   = (const int*)  d_in[3];
    const float* zt    = (const float*)d_in[4];
    const float* zln_w = (const float*)d_in[5];
    const float* zln_b = (const float*)d_in[6];
    const float* W1    = (const float*)d_in[7];
    const float* b1    = (const float*)d_in[8];
    const float* W2    = (const float*)d_in[9];
    const float* b2    = (const float*)d_in[10];
    const float* W3    = (const float*)d_in[11];
    const float* b3    = (const float*)d_in[12];
    const float* eln_w = (const float*)d_in[13];
    const float* eln_b = (const float*)d_in[14];

    int N = in_sizes[0];
    int E = in_sizes[2];

    float* out_node = (float*)d_out;
    float* out_edge = out_node + (size_t)N * CC;

    cudaFuncSetAttribute(mlp_kernel, cudaFuncAttributeMaxDynamicSharedMemorySize, SMEM_BYTES);

    // lazily created once (first call is the uncaptured correctness run); reused thereafter.
    static cudaStream_t s2 = nullptr, s3 = nullptr;
    static cudaEvent_t eFork = nullptr, ePrep = nullptr, ePrepw = nullptr, eS3 = nullptr;
    if (!s2) {
        cudaStreamCreateWithFlags(&s2, cudaStreamNonBlocking);
        cudaStreamCreateWithFlags(&s3, cudaStreamNonBlocking);
        cudaEventCreateWithFlags(&eFork,  cudaEventDisableTiming);
        cudaEventCreateWithFlags(&ePrep,  cudaEventDisableTiming);
        cudaEventCreateWithFlags(&ePrepw, cudaEventDisableTiming);
        cudaEventCreateWithFlags(&eS3,    cudaEventDisableTiming);
    }

    // fork s2 and s3 from the capture-origin (default) stream
    cudaEventRecord(eFork, 0);
    cudaStreamWaitEvent(s2, eFork, 0);
    cudaStreamWaitEvent(s3, eFork, 0);

    // --- stream0 (critical path): reset -> prep -> [prepw join] -> mlp ---
    reset_kernel<<<1, 1, 0, 0>>>();
    prep_kernel<<<(E + 255) / 256, 256, 0, 0>>>(pos, snd, rcv, E);
    cudaEventRecord(ePrep, 0);

    // --- s2: weight packing (independent of edge classification) ---
    prepw_kernel<<<480, 256, 0, s2>>>(W1, W2, W3);
    cudaEventRecord(ePrepw, s2);

    // --- s3: node LN, const row, then fill (needs prep's inactive list) ---
    node_kernel<<<(N + 7) / 8, 256, 0, s3>>>(Z, zt, zln_w, zln_b, out_node, N);
    const_row_kernel<<<1, 1024, 0, s3>>>(b1, W2, b2, W3, b3, eln_w, eln_b);
    cudaStreamWaitEvent(s3, ePrep, 0);
    fill_kernel<<<(E + 7) / 8, 256, 0, s3>>>(out_edge);
    cudaEventRecord(eS3, s3);

    // mlp needs prep (ordered on stream0) + packed weights
    cudaStreamWaitEvent(0, ePrepw, 0);
    mlp_kernel<<<(E + 63) / 64, 256, SMEM_BYTES, 0>>>(pos, snd, rcv,
                                                      b1, b2, b3, eln_w, eln_b, out_edge);
    // join s3 back into the origin stream so the captured graph is complete
    cudaStreamWaitEvent(0, eS3, 0);
}